// round 13
// baseline (speedup 1.0000x reference)
#include <cuda_runtime.h>
#include <math.h>

// Problem constants
constexpr int T  = 2048;
constexpr int B  = 64;
constexpr int H  = 128;
constexpr int G  = 512;   // 4*H gate rows
constexpr int IN = 128;

constexpr int CH     = 128;      // producer/consumer chunk (timesteps)
constexpr int NCHUNK = T / CH;   // 16
constexpr int RECC0  = 32;       // rec0 CTAs (2 batches each)
constexpr int NG     = 80;       // gemm CTAs (10 per gc)
constexpr int RECC1  = 32;       // rec1 CTAs (2 batches each)
constexpr int LOOKAHEAD = 2;     // xp0 chunks produced ahead of rec0

typedef unsigned long long u64;

// ---------------------------------------------------------------------------
// Scratch (static __device__ arrays — no allocation in kernel_launch)
// ---------------------------------------------------------------------------
__device__ float g_xp0[(size_t)T * B * G];  // layer-0 input projections (+bias)
__device__ float g_xp1[(size_t)T * B * G];  // layer-1 input projections (+bias)
__device__ float g_hs[(size_t)T * B * H];   // layer-0 hidden states
__device__ float g_hT[B * H];               // final hidden of layer 1
// Per-chunk completion counters (drift-proof vs a single cumulative counter)
__device__ int   g_xp0_done[NCHUNK];        // == NG when chunk fully written
__device__ int   g_h0_done[NCHUNK];         // == RECC0
__device__ int   g_xp1_done[NCHUNK];        // == NG

__global__ void reset_flags() {
    for (int i = 0; i < NCHUNK; i++) {
        g_xp0_done[i] = 0; g_h0_done[i] = 0; g_xp1_done[i] = 0;
    }
}

// ---------------------------------------------------------------------------
// Packed fp32x2 helpers (PTX ISA 8.6+, sm_100+)
// ---------------------------------------------------------------------------
__device__ __forceinline__ u64 ffma2(u64 a, u64 b, u64 c) {
    u64 d;
    asm("fma.rn.f32x2 %0, %1, %2, %3;" : "=l"(d) : "l"(a), "l"(b), "l"(c));
    return d;
}
__device__ __forceinline__ u64 pack_dup(float a) {
    u64 d; asm("mov.b64 %0, {%1, %1};" : "=l"(d) : "f"(a)); return d;
}
__device__ __forceinline__ u64 pack2(float x, float y) {
    u64 d; asm("mov.b64 %0, {%1, %2};" : "=l"(d) : "f"(x), "f"(y)); return d;
}
__device__ __forceinline__ float2 unpack2(u64 a) {
    float2 r; asm("mov.b64 {%0, %1}, %2;" : "=f"(r.x), "=f"(r.y) : "l"(a)); return r;
}
__device__ __forceinline__ float hadd2(u64 a) {
    float2 r = unpack2(a); return r.x + r.y;
}
__device__ __forceinline__ float sigf(float x) {
    return __fdividef(1.f, 1.f + __expf(-x));
}
__device__ __forceinline__ float tanh_fast(float x) {
    return 1.f - __fdividef(2.f, __expf(2.f * x) + 1.f);
}

// spin-wait on a per-chunk counter (one thread polls, CTA-wide release)
__device__ __forceinline__ void wait_flag(volatile int* flag, int target, int tid) {
    if (tid == 0) {
        while (*flag < target) { __nanosleep(200); }
    }
    __syncthreads();
    __threadfence();   // acquire: order subsequent gmem reads after the flag
}

// ---------------------------------------------------------------------------
// 2-batch LSTM recurrence body. 256 threads, batches (b0, b0+1).
// Thread owns gate rows (tid, 256+tid) for BOTH batches (weights shared).
// Weight cols 0..79 in regs (40 u64/row), cols 80..127 in smem (12 ull2/row).
// CONSUME: gate x-prefetch on per-chunk flags (target NG).
// PUBLISH: bump g_h0_done[chunk] after chunk's g_hs writes are fenced.
// ---------------------------------------------------------------------------
constexpr int REC2_SMEM = 12 * 2 * 256 * 16 + 2 * 128 * 4 + 2 * 256 * 8; // 103,424 B

template<bool WRITE_ALL, bool PUBLISH, bool CONSUME>
__device__ __forceinline__ void rec_body2(const float* __restrict__ Whh,
                                          const float* __restrict__ xp,
                                          volatile int* cons_flags,
                                          float* smbase, int b0)
{
    ulonglong2* wsmq   = (ulonglong2*)smbase;            // [(q*2+row)*256 + tid]
    float*      hbuf0  = smbase + 12 * 2 * 256 * 4;      // 128 floats
    float*      hbuf1  = hbuf0 + 128;                    // 128 floats
    u64*        gat0   = (u64*)(hbuf1 + 128);            // 256 packed pairs
    u64*        gat1   = gat0 + 256;

    const int tid  = threadIdx.x;
    const int rowA = tid;
    const int rowB = 256 + tid;

    u64 wrA[40], wrB[40];
    {
        const u64* pa = (const u64*)(Whh + rowA * IN);
        const u64* pb = (const u64*)(Whh + rowB * IN);
        #pragma unroll
        for (int i = 0; i < 40; i++) { wrA[i] = pa[i]; wrB[i] = pb[i]; }
    }
    {
        const ulonglong2* ta = (const ulonglong2*)(Whh + rowA * IN + 80);
        const ulonglong2* tb = (const ulonglong2*)(Whh + rowB * IN + 80);
        #pragma unroll
        for (int q = 0; q < 12; q++) {
            wsmq[(q * 2 + 0) * 256 + tid] = ta[q];
            wsmq[(q * 2 + 1) * 256 + tid] = tb[q];
        }
    }
    if (tid < H) { hbuf0[tid] = 0.f; hbuf1[tid] = 0.f; }
    float cc = 0.f;   // cell state for (batch = tid>>7, unit = tid&127)

    if (CONSUME) wait_flag(&cons_flags[0], NG, tid);   // chunk 0 ready

    const float* xpb0 = xp + (size_t)b0 * G;
    const float* xpb1 = xp + (size_t)(b0 + 1) * G;
    float xa0 = xpb0[rowA], xb0 = xpb0[rowB];
    float xa1 = xpb1[rowA], xb1 = xpb1[rowB];
    const bool tanhB = (tid < 128);
    __syncthreads();

    #pragma unroll 1
    for (int t = 0; t < T; t++) {
        const ulonglong2* h0q = (const ulonglong2*)hbuf0;
        const ulonglong2* h1q = (const ulonglong2*)hbuf1;
        u64 aA0 = 0ull, aA1 = 0ull, aB0 = 0ull, aB1 = 0ull;   // batch0
        u64 cA0 = 0ull, cA1 = 0ull, cB0 = 0ull, cB1 = 0ull;   // batch1
        #pragma unroll
        for (int q = 0; q < 20; q++) {
            const ulonglong2 h0v = h0q[q];
            const ulonglong2 h1v = h1q[q];
            const u64 wa0 = wrA[2 * q], wa1 = wrA[2 * q + 1];
            const u64 wb0 = wrB[2 * q], wb1 = wrB[2 * q + 1];
            aA0 = ffma2(wa0, h0v.x, aA0);
            aA1 = ffma2(wa1, h0v.y, aA1);
            aB0 = ffma2(wb0, h0v.x, aB0);
            aB1 = ffma2(wb1, h0v.y, aB1);
            cA0 = ffma2(wa0, h1v.x, cA0);
            cA1 = ffma2(wa1, h1v.y, cA1);
            cB0 = ffma2(wb0, h1v.x, cB0);
            cB1 = ffma2(wb1, h1v.y, cB1);
        }
        #pragma unroll
        for (int q = 0; q < 12; q++) {
            const ulonglong2 h0v = h0q[20 + q];
            const ulonglong2 h1v = h1q[20 + q];
            const ulonglong2 wa = wsmq[(q * 2 + 0) * 256 + tid];
            const ulonglong2 wb = wsmq[(q * 2 + 1) * 256 + tid];
            aA0 = ffma2(wa.x, h0v.x, aA0);
            aA1 = ffma2(wa.y, h0v.y, aA1);
            aB0 = ffma2(wb.x, h0v.x, aB0);
            aB1 = ffma2(wb.y, h0v.y, aB1);
            cA0 = ffma2(wa.x, h1v.x, cA0);
            cA1 = ffma2(wa.y, h1v.y, cA1);
            cB0 = ffma2(wb.x, h1v.x, cB0);
            cB1 = ffma2(wb.y, h1v.y, cB1);
        }
        const float gA0 = hadd2(aA0) + hadd2(aA1) + xa0;
        const float gB0 = hadd2(aB0) + hadd2(aB1) + xb0;
        const float gA1 = hadd2(cA0) + hadd2(cA1) + xa1;
        const float gB1 = hadd2(cB0) + hadd2(cB1) + xb1;
        const float actA0 = sigf(gA0);
        const float actB0 = tanhB ? tanh_fast(gB0) : sigf(gB0);
        const float actA1 = sigf(gA1);
        const float actB1 = tanhB ? tanh_fast(gB1) : sigf(gB1);
        if (t + 1 < T) {
            if (CONSUME && (((t + 1) & (CH - 1)) == 0)) {
                wait_flag(&cons_flags[(t + 1) / CH], NG, tid);
            }
            const size_t off = (size_t)(t + 1) * (B * G);
            xa0 = xpb0[off + rowA]; xb0 = xpb0[off + rowB];
            xa1 = xpb1[off + rowA]; xb1 = xpb1[off + rowB];
        }
        gat0[tid] = pack2(actA0, actB0);
        gat1[tid] = pack2(actA1, actB1);
        __syncthreads();
        {
            const int unit = tid & 127;
            const int bat  = tid >> 7;
            u64*   gsel = bat ? gat1 : gat0;
            float* hsel = bat ? hbuf1 : hbuf0;
            const float2 ig = unpack2(gsel[unit]);          // (i, g)
            const float2 fo = unpack2(gsel[unit + 128]);    // (f, o)
            cc = fo.x * cc + ig.x * ig.y;
            const float h = fo.y * tanh_fast(cc);
            hsel[unit] = h;
            if (WRITE_ALL) {
                g_hs[((size_t)t * B + b0 + bat) * H + unit] = h;
            } else if (t == T - 1) {
                g_hT[(b0 + bat) * H + unit] = h;
            }
        }
        __syncthreads();
        if (PUBLISH && ((t & (CH - 1)) == CH - 1)) {
            __threadfence();          // release this chunk's g_hs
            __syncthreads();
            if (tid == 0) atomicAdd(&g_h0_done[t / CH], 1);
        }
    }
}

// ---------------------------------------------------------------------------
// GEMM tile compute (64b x 64g, K=128) from smem.
// ---------------------------------------------------------------------------
__device__ __forceinline__ void gemm_tile(const float* Ws, const float* As,
                                          const float* bias, float* outp)
{
    const int tid  = threadIdx.x;
    const int bb   = tid >> 3;
    const int gblk = tid & 7;

    u64 acc[8];
    #pragma unroll
    for (int i = 0; i < 8; i++) acc[i] = 0ull;

    #pragma unroll 8
    for (int k = 0; k < 128; k++) {
        const u64 a0 = pack_dup(As[bb * 136 + k]);
        const u64 a1 = pack_dup(As[(bb + 32) * 136 + k]);
        const ulonglong2* wp = (const ulonglong2*)&Ws[k * 68 + gblk * 8];
        const ulonglong2 wlo = wp[0], whi = wp[1];
        acc[0] = ffma2(wlo.x, a0, acc[0]);
        acc[1] = ffma2(wlo.y, a0, acc[1]);
        acc[2] = ffma2(whi.x, a0, acc[2]);
        acc[3] = ffma2(whi.y, a0, acc[3]);
        acc[4] = ffma2(wlo.x, a1, acc[4]);
        acc[5] = ffma2(wlo.y, a1, acc[5]);
        acc[6] = ffma2(whi.x, a1, acc[6]);
        acc[7] = ffma2(whi.y, a1, acc[7]);
    }

    #pragma unroll
    for (int half = 0; half < 2; half++) {
        const int row = bb + half * 32;
        float4 o0, o1;
        float2 p0 = unpack2(acc[half * 4 + 0]);
        float2 p1 = unpack2(acc[half * 4 + 1]);
        float2 p2 = unpack2(acc[half * 4 + 2]);
        float2 p3 = unpack2(acc[half * 4 + 3]);
        o0.x = p0.x + bias[0]; o0.y = p0.y + bias[1];
        o0.z = p1.x + bias[2]; o0.w = p1.y + bias[3];
        o1.x = p2.x + bias[4]; o1.y = p2.y + bias[5];
        o1.z = p3.x + bias[6]; o1.w = p3.y + bias[7];
        float* op = outp + (size_t)row * G;
        ((float4*)op)[0] = o0;
        ((float4*)op)[1] = o1;
    }
}

// GEMM-role smem: Ws0 + Ws1 + As
constexpr int GEMMF_SMEM = (2 * 128 * 68 + 64 * 136) * 4;   // 104,448 B
constexpr int FUSED_SMEM = (GEMMF_SMEM > REC2_SMEM) ? GEMMF_SMEM : REC2_SMEM;

// ---------------------------------------------------------------------------
// FULLY-FUSED kernel: gemm (80 CTAs: xp0 with 2-chunk lookahead + xp1) +
// rec0 (32 CTAs, 2 batches) + rec1 (32 CTAs, 2 batches) = 144 CTAs at
// 1 CTA/SM <= 148 SMs -> whole grid is wave 1 -> co-resident, deadlock-free.
// Acyclic flag chain: gemm -> xp0_done -> rec0 -> h0_done -> gemm ->
// xp1_done -> rec1. Gemm publishes xp0 chunk c+2 BEFORE blocking on h0[c],
// and rec0 needs at most chunk c+1 to finish chunk c -> margin of 1 chunk.
// ---------------------------------------------------------------------------
__global__ __launch_bounds__(256, 1)
void fused_pipeline(const float* __restrict__ mapf,
                    const float* __restrict__ pos,
                    const float* __restrict__ Wih0,
                    const float* __restrict__ bih0,
                    const float* __restrict__ bhh0,
                    const float* __restrict__ Whh0,
                    const float* __restrict__ Wih1,
                    const float* __restrict__ bih1,
                    const float* __restrict__ bhh1,
                    const float* __restrict__ Whh1)
{
    extern __shared__ float sm[];
    const int tid = threadIdx.x;
    const int bid = blockIdx.x;

    if (bid < RECC0) {
        rec_body2<true, true, true>(Whh0, g_xp0, g_xp0_done, sm, 2 * bid);
        return;
    }
    if (bid >= RECC0 + NG) {
        rec_body2<false, false, true>(Whh1, g_xp1, g_xp1_done, sm,
                                      2 * (bid - RECC0 - NG));
        return;
    }

    // ---- gemm role ----
    const int idx = bid - RECC0;         // 0..NG-1
    const int gc  = idx & 7;
    const int sub = idx >> 3;            // 0..9
    float* Ws0 = sm;                      // [128][68] Wih0 k-major
    float* Ws1 = sm + 128 * 68;           // [128][68] Wih1 k-major
    float* As  = sm + 2 * 128 * 68;       // [64][136]

    for (int i = tid; i < 64 * 128; i += 256) {
        const int k = i & 127;
        const int g = i >> 7;
        Ws0[k * 68 + g] = Wih0[(gc * 64 + g) * IN + k];
        Ws1[k * 68 + g] = Wih1[(gc * 64 + g) * IN + k];
    }

    const int gblk = tid & 7;
    const int gbase = gc * 64 + gblk * 8;
    float bias0[8], bias1[8];
    #pragma unroll
    for (int i = 0; i < 8; i++) {
        bias0[i] = bih0[gbase + i] + bhh0[gbase + i];
        bias1[i] = bih1[gbase + i] + bhh1[gbase + i];
    }

    // xp0 chunk producer (layer-0 inputs from mapf/pos)
    auto do_xp0 = [&](int c) {
        for (int tl = sub; tl < CH; tl += 10) {
            const int t = c * CH + tl;
            __syncthreads();
            for (int i = tid; i < 64 * 128; i += 256) {
                const int k = i & 127;
                const int r = i >> 7;
                const float v = (k < 126) ? mapf[((size_t)r * T + t) * 126 + k]
                                          : pos[((size_t)r * T + t) * 2 + (k - 126)];
                As[r * 136 + k] = v;
            }
            __syncthreads();
            gemm_tile(Ws0, As, bias0, g_xp0 + (size_t)t * B * G + gbase);
        }
        __threadfence();
        __syncthreads();
        if (tid == 0) atomicAdd(&g_xp0_done[c], 1);
    };
    // xp1 chunk producer (layer-1 inputs from g_hs)
    auto do_xp1 = [&](int c) {
        for (int tl = sub; tl < CH; tl += 10) {
            const int t = c * CH + tl;
            __syncthreads();
            const float4* src = (const float4*)(g_hs + (size_t)t * B * H);
            #pragma unroll
            for (int j = 0; j < 8; j++) {
                const int i4 = tid + j * 256;
                const int r  = i4 >> 5;
                const int k4 = i4 & 31;
                ((float4*)&As[r * 136 + k4 * 4])[0] = src[i4];
            }
            __syncthreads();
            gemm_tile(Ws1, As, bias1, g_xp1 + (size_t)t * B * G + gbase);
        }
        __threadfence();
        __syncthreads();
        if (tid == 0) atomicAdd(&g_xp1_done[c], 1);
    };

    // Prime the lookahead, then alternate: stay >= LOOKAHEAD xp0 chunks
    // ahead of the h0 chunk we block on.
    for (int p = 0; p < LOOKAHEAD && p < NCHUNK; p++) do_xp0(p);
    for (int c = 0; c < NCHUNK; c++) {
        if (c + LOOKAHEAD < NCHUNK) do_xp0(c + LOOKAHEAD);
        wait_flag(&g_h0_done[c], RECC0, tid);
        do_xp1(c);
    }
}

// ---------------------------------------------------------------------------
// MLP head: one CTA per batch row, 64 threads.
// ---------------------------------------------------------------------------
__global__ void head_kernel(const float* __restrict__ W1, const float* __restrict__ b1,
                            const float* __restrict__ lng, const float* __restrict__ lnb,
                            const float* __restrict__ W2, const float* __restrict__ b2,
                            float* __restrict__ out)
{
    __shared__ float hb[128];
    __shared__ float red[64];
    __shared__ float bc;
    const int b = blockIdx.x;
    const int j = threadIdx.x;

    hb[j]      = g_hT[b * H + j];
    hb[j + 64] = g_hT[b * H + 64 + j];
    __syncthreads();

    float acc = b1[j];
    #pragma unroll 8
    for (int k = 0; k < H; k++) acc += hb[k] * W1[j * H + k];

    red[j] = acc; __syncthreads();
    if (j == 0) { float s = 0.f; for (int k = 0; k < 64; k++) s += red[k]; bc = s * (1.f / 64.f); }
    __syncthreads();
    const float mu = bc;
    const float d  = acc - mu;

    red[j] = d * d; __syncthreads();
    if (j == 0) { float s = 0.f; for (int k = 0; k < 64; k++) s += red[k]; bc = s * (1.f / 64.f); }
    __syncthreads();
    const float var = bc;

    float v = d * rsqrtf(var + 1e-5f) * lng[j] + lnb[j];
    v = (v >= 0.f) ? v : 0.2f * v;

    red[j] = v * W2[j]; __syncthreads();
    if (j == 0) { float s = 0.f; for (int k = 0; k < 64; k++) s += red[k]; out[b] = s + b2[0]; }
}

// ---------------------------------------------------------------------------
// Launch: reset -> fused(gemm0 || rec0 || gemm1 || rec1) -> head
// ---------------------------------------------------------------------------
extern "C" void kernel_launch(void* const* d_in, const int* in_sizes, int n_in,
                              void* d_out, int out_size)
{
    const float* mapf = (const float*)d_in[0];
    const float* pos  = (const float*)d_in[1];
    const float* Wih0 = (const float*)d_in[2];
    const float* Whh0 = (const float*)d_in[3];
    const float* bih0 = (const float*)d_in[4];
    const float* bhh0 = (const float*)d_in[5];
    const float* Wih1 = (const float*)d_in[6];
    const float* Whh1 = (const float*)d_in[7];
    const float* bih1 = (const float*)d_in[8];
    const float* bhh1 = (const float*)d_in[9];
    const float* W1   = (const float*)d_in[10];
    const float* b1   = (const float*)d_in[11];
    const float* lng  = (const float*)d_in[12];
    const float* lnb  = (const float*)d_in[13];
    const float* W2   = (const float*)d_in[14];
    const float* b2   = (const float*)d_in[15];
    float* out = (float*)d_out;

    cudaFuncSetAttribute((const void*)fused_pipeline,
                         cudaFuncAttributeMaxDynamicSharedMemorySize, FUSED_SMEM);

    reset_flags<<<1, 1>>>();
    fused_pipeline<<<RECC0 + NG + RECC1, 256, FUSED_SMEM>>>(
        mapf, pos, Wih0, bih0, bhh0, Whh0, Wih1, bih1, bhh1, Whh1);
    head_kernel<<<B, 64>>>(W1, b1, lng, lnb, W2, b2, out);
}